// round 15
// baseline (speedup 1.0000x reference)
#include <cuda_runtime.h>
#include <cuda_bf16.h>
#include <math.h>

#define BN     8192
#define ZD     128
#define NC     62
#define NP     93
#define P2     96        // padded proxies
#define NA     2730      // anchors 0,3,...,8187
#define EPSV   1e-6f
#define EPS2T  1.28e-10f // ZD*EPS^2
#define SZP    132       // padded smem row pitch (floats) for z AND prx
#define SDP    68        // padded dpz-transpose pitch
#define DTHR   512       // 16 warps; warp = 4 samples x 96 proxies
#define HB_W   8         // anchors (warps) per k_hard block
#define HGRID  ((NA + HB_W - 1) / HB_W)   // 342
#define NBPRE  16        // k_pre blocks (co-resident; spin barrier)
#define TPRE   512

#define SMEM_Z_FLOATS  (64 * SZP)     // 8448 (overlaid by s_dpz 96*68=6528)
#define SMEM_P_FLOATS  (P2 * SZP)     // 12672
#define SMEM_DYN_BYTES ((SMEM_Z_FLOATS + SMEM_P_FLOATS) * 4)   // 84480

// ---------------- persistent scratch (device globals, zero-init) -------------
__device__ float g_prxT[P2 * ZD];      // [p][k] normalized; rows 93..95 stay 0
__device__ float g_pss[P2];            // pads stay 0
__device__ float g_psum[P2];
__device__ int   g_ph[NBPRE * NC];     // partial histograms
__device__ int   g_perm[BN];           // pos -> sample index j (class-sorted)
__device__ int4  g_meta[NA];           // .x = nearest proxy, .y = lo, .z = hi
__device__ float g_Dpz[P2 * BN];       // dist(proxy p, z[perm[pos]]), [p][pos]
__device__ float g_DT [BN * P2];       // dist(z[perm[pos]], proxy p), [pos][p]
__device__ float g_loss[NA];
__device__ unsigned int g_done;
__device__ unsigned int g_barcnt;
__device__ volatile unsigned int g_bargen;   // monotonic across replays

// ---------------- helpers ---------------------------------------------------
__device__ __forceinline__ float warp_sum(float v) {
#pragma unroll
    for (int o = 16; o; o >>= 1) v += __shfl_xor_sync(0xffffffffu, v, o);
    return v;
}
__device__ __forceinline__ void warp_argmin(float& v, int& i) {
#pragma unroll
    for (int o = 16; o; o >>= 1) {
        float v2 = __shfl_xor_sync(0xffffffffu, v, o);
        int   i2 = __shfl_xor_sync(0xffffffffu, i, o);
        if (v2 < v || (v2 == v && i2 < i)) { v = v2; i = i2; }
    }
}

// ============ K0: perm + bounds + proxy normalize (partial hist + barrier) ===
// grid: NBPRE x TPRE
__global__ void __launch_bounds__(TPRE) k_pre(const int* __restrict__ y_idx,
                                              const int* __restrict__ y_map,
                                              const float* __restrict__ proxies) {
    __shared__ int s_inv[NC];
    __shared__ int s_hist[NC];
    __shared__ int s_colsum[NC], s_mine[NC], s_cur[NC];
    __shared__ int s_start[NC];
    __shared__ int s_base[NC];
    __shared__ int s_cls[TPRE];
    int b = blockIdx.x, t = threadIdx.x;
    int w = t >> 5, lane = t & 31;

    if (t < NC) { s_inv[y_map[t]] = t; s_hist[t] = 0; }
    __syncthreads();

    // ---- phase 1: partial histogram of my 512-label slice ----
    int myc = s_inv[y_idx[b * TPRE + t]];
    s_cls[t] = myc;
    atomicAdd(&s_hist[myc], 1);
    __syncthreads();
    if (t < NC) g_ph[b * NC + t] = s_hist[t];

    // ---- independent work hidden under barrier: proxy normalization ----
    // warp w of block b owns proxy p = b + 16*w (unique over 0..255)
    int p = b + NBPRE * w;
    if (p < NP) {
        float4 v = ((const float4*)(proxies + p * ZD))[lane];
        float ss = warp_sum(v.x * v.x + v.y * v.y + v.z * v.z + v.w * v.w);
        float inv = 1.f / fmaxf(sqrtf(ss), 1e-12f);
        float4 o = make_float4(v.x * inv, v.y * inv, v.z * inv, v.w * inv);
        ((float4*)(g_prxT + p * ZD))[lane] = o;
        float so  = warp_sum(o.x + o.y + o.z + o.w);
        float so2 = warp_sum(o.x * o.x + o.y * o.y + o.z * o.z + o.w * o.w);
        if (lane == 0) { g_psum[p] = so; g_pss[p] = so2; }
    }

    // ---- spin barrier across NBPRE co-resident blocks ----
    __syncthreads();
    if (t == 0) {
        __threadfence();
        unsigned gen = g_bargen;
        if (atomicAdd(&g_barcnt, 1u) == NBPRE - 1) {
            g_barcnt = 0;
            __threadfence();
            g_bargen = gen + 1;
        } else {
            while (g_bargen == gen) { }
        }
        __threadfence();
    }
    __syncthreads();

    // ---- phase 2: column sums + my prefix (16 adds per class) ----
    if (t < NC) {
        int tot = 0, mine = 0;
#pragma unroll
        for (int bb = 0; bb < NBPRE; bb++) {
            int v = g_ph[bb * NC + t];
            if (bb < b) mine += v;
            tot += v;
        }
        s_colsum[t] = tot;
        s_mine[t] = mine;
        s_cur[t] = 0;
    }
    __syncthreads();
    // warp0: exclusive scan of 62 class totals via shuffles
    if (w == 0) {
        int c1 = lane + 32;
        int v0 = s_colsum[lane];
        int v1 = (c1 < NC) ? s_colsum[c1] : 0;
        int x0 = v0, x1 = v1;
#pragma unroll
        for (int o = 1; o < 32; o <<= 1) {
            int y0 = __shfl_up_sync(0xffffffffu, x0, o);
            int y1 = __shfl_up_sync(0xffffffffu, x1, o);
            if (lane >= o) { x0 += y0; x1 += y1; }
        }
        int tot0 = __shfl_sync(0xffffffffu, x0, 31);
        s_start[lane] = x0 - v0;
        if (c1 < NC) s_start[c1] = tot0 + x1 - v1;
    }
    __syncthreads();
    if (t < NC) s_base[t] = s_start[t] + s_mine[t];
    __syncthreads();

    // scatter my slice (local rank atomics only)
    {
        int c = myc;
        int r = atomicAdd(&s_cur[c], 1);
        g_perm[s_base[c] + r] = b * TPRE + t;
    }
    // per-anchor class bounds (global thread index covers 0..8191 >= NA)
    int gi = b * TPRE + t;
    if (gi < NA) {
        int c = s_inv[y_idx[3 * gi]];
        g_meta[gi].y = s_start[c];
        g_meta[gi].z = s_start[c] + s_colsum[c];
    }
}

// ============ K1: distances over permuted samples + nearest-proxy ============
// grid: 128 x 512. Block b handles pos range [64b, 64b+64).
__global__ void __launch_bounds__(DTHR) k_dist(const float* __restrict__ z) {
    extern __shared__ float smem[];
    float* s_z   = smem;                  // [64][SZP]; reused as s_dpz[96][SDP]
    float* s_prx = smem + SMEM_Z_FLOATS;  // [P2][SZP]  row-major [p][k]
    __shared__ float s_zz[64], s_zs[64];
    __shared__ float s_pss[P2], s_psum[P2];
    __shared__ int   s_perm[64];

    int b = blockIdx.x, t = threadIdx.x;
    int w = t >> 5, lane = t & 31;
    int B0 = b * 64;

    if (t < 64) s_perm[t] = g_perm[B0 + t];
    if (t < P2) { s_pss[t] = g_pss[t]; s_psum[t] = g_psum[t]; }   // pads are 0
    __syncthreads();

    // ---- stage 64 permuted z rows (row-coalesced; free per-row stats) ----
    const float4* z4 = (const float4*)z;
    for (int idx = t; idx < 64 * 32; idx += DTHR) {
        int r = idx >> 5, q = idx & 31;          // r warp-uniform
        float4 v = z4[(size_t)s_perm[r] * 32 + q];
        *(float4*)&s_z[r * SZP + 4 * q] = v;
        float s  = (v.x + v.y) + (v.z + v.w);
        float ss = (v.x * v.x + v.y * v.y) + (v.z * v.z + v.w * v.w);
#pragma unroll
        for (int o = 16; o; o >>= 1) {
            s  += __shfl_xor_sync(0xffffffffu, s, o);
            ss += __shfl_xor_sync(0xffffffffu, ss, o);
        }
        if (lane == 0) { s_zs[r] = s; s_zz[r] = ss; }
    }
    // ---- stage normalized proxies (coalesced; pad rows are global zeros) ----
    const float4* gp4 = (const float4*)g_prxT;
    for (int idx = t; idx < P2 * 32; idx += DTHR) {
        int p = idx >> 5, q = idx & 31;
        *(float4*)&s_prx[p * SZP + 4 * q] = gp4[idx];
    }
    __syncthreads();

    // ---- mainloop: warp = samples [4w,4w+4) x 96 proxies, float4 over k ----
    int sl = 4 * w;
    const float* pr0 = &s_prx[(lane)      * SZP];
    const float* pr1 = &s_prx[(lane + 32) * SZP];
    const float* pr2 = &s_prx[(lane + 64) * SZP];
    const float* zr0 = &s_z[(sl + 0) * SZP];
    const float* zr1 = &s_z[(sl + 1) * SZP];
    const float* zr2 = &s_z[(sl + 2) * SZP];
    const float* zr3 = &s_z[(sl + 3) * SZP];

    float acc[3][4];
#pragma unroll
    for (int q = 0; q < 3; q++)
#pragma unroll
        for (int i = 0; i < 4; i++) acc[q][i] = 0.f;

#pragma unroll 4
    for (int k4 = 0; k4 < 32; k4++) {
        int ko = 4 * k4;
        float4 p0 = *(const float4*)&pr0[ko];   // conflict-free (132-pitch)
        float4 p1 = *(const float4*)&pr1[ko];
        float4 p2 = *(const float4*)&pr2[ko];
        float4 zv0 = *(const float4*)&zr0[ko];  // broadcasts
        float4 zv1 = *(const float4*)&zr1[ko];
        float4 zv2 = *(const float4*)&zr2[ko];
        float4 zv3 = *(const float4*)&zr3[ko];
#define DOT4(q, pv, i, zv) \
        acc[q][i] = fmaf(pv.x, zv.x, acc[q][i]); \
        acc[q][i] = fmaf(pv.y, zv.y, acc[q][i]); \
        acc[q][i] = fmaf(pv.z, zv.z, acc[q][i]); \
        acc[q][i] = fmaf(pv.w, zv.w, acc[q][i]);
        DOT4(0, p0, 0, zv0) DOT4(0, p0, 1, zv1) DOT4(0, p0, 2, zv2) DOT4(0, p0, 3, zv3)
        DOT4(1, p1, 0, zv0) DOT4(1, p1, 1, zv1) DOT4(1, p1, 2, zv2) DOT4(1, p1, 3, zv3)
        DOT4(2, p2, 0, zv0) DOT4(2, p2, 1, zv1) DOT4(2, p2, 2, zv2) DOT4(2, p2, 3, zv3)
#undef DOT4
    }

    // ---- epilogue: distances; DT rows direct; Dpz via smem transpose ----
    float pss0 = s_pss[lane],      psm0 = s_psum[lane];
    float pss1 = s_pss[lane + 32], psm1 = s_psum[lane + 32];
    float pss2 = s_pss[lane + 64], psm2 = s_psum[lane + 64];
    float zzv[4], zsv[4];
    int   jglob[4];
#pragma unroll
    for (int i = 0; i < 4; i++) {
        zzv[i] = s_zz[sl + i]; zsv[i] = s_zs[sl + i];
        jglob[i] = s_perm[sl + i];
    }

    __syncthreads();                       // all mainloop smem reads done
    float* s_dpz = s_z;                    // overlay: [96][SDP]

#pragma unroll
    for (int i = 0; i < 4; i++) {
        int pos = B0 + sl + i;
        float base0 = zzv[i] + pss0 - 2.f * acc[0][i];
        float base1 = zzv[i] + pss1 - 2.f * acc[1][i];
        float base2 = zzv[i] + pss2 - 2.f * acc[2][i];
        float e0 = 2.f * EPSV * (psm0 - zsv[i]);
        float e1 = 2.f * EPSV * (psm1 - zsv[i]);
        float e2 = 2.f * EPSV * (psm2 - zsv[i]);
        float dpz0 = sqrtf(fmaxf(base0 + e0 + EPS2T, 0.f));
        float dpz1 = sqrtf(fmaxf(base1 + e1 + EPS2T, 0.f));
        float dpz2 = sqrtf(fmaxf(base2 + e2 + EPS2T, 0.f));
        float dzp0 = sqrtf(fmaxf(base0 - e0 + EPS2T, 0.f));
        float dzp1 = sqrtf(fmaxf(base1 - e1 + EPS2T, 0.f));
        float dzp2 = sqrtf(fmaxf(base2 - e2 + EPS2T, 0.f));

        // DT: coalesced row writes (pos-major)
        float* dt = g_DT + (size_t)pos * P2;
        dt[lane] = dzp0; dt[lane + 32] = dzp1; dt[lane + 64] = dzp2;

        // dpz into transpose buffer
        int sc = sl + i;
        s_dpz[(lane)      * SDP + sc] = dpz0;
        s_dpz[(lane + 32) * SDP + sc] = dpz1;
        s_dpz[(lane + 64) * SDP + sc] = dpz2;

        // nearest-proxy argmin for anchor rows (dzp in registers)
        int j = jglob[i];                       // warp-uniform
        if (j % 3 == 0 && j / 3 < NA) {
            float bv = dzp0; int bp = lane;
            if (lane + 32 < NP && dzp1 < bv) { bv = dzp1; bp = lane + 32; }
            if (lane + 64 < NP && dzp2 < bv) { bv = dzp2; bp = lane + 64; }
            warp_argmin(bv, bp);
            if (lane == 0) g_meta[j / 3].x = bp;
        }
    }
    __syncthreads();

    // coalesced Dpz row writes: 96 rows x 64 floats (pos-major columns)
    for (int idx = t; idx < 96 * 16; idx += DTHR) {
        int p = idx >> 4, q = idx & 15;
        float4 v = make_float4(s_dpz[p * SDP + 4 * q],     s_dpz[p * SDP + 4 * q + 1],
                               s_dpz[p * SDP + 4 * q + 2], s_dpz[p * SDP + 4 * q + 3]);
        *(float4*)(g_Dpz + (size_t)p * BN + B0 + 4 * q) = v;
    }
}

// ============ K2: warp-per-anchor, fully coalesced candidate reads ===========
// grid: HGRID x 256
__global__ void __launch_bounds__(256) k_hard(float* __restrict__ out) {
    __shared__ float rbuf[8];
    __shared__ int s_last;
    int t = threadIdx.x, w = t >> 5, lane = t & 31;
    int i = blockIdx.x * HB_W + w;

    if (i < NA) {
        int a = 3 * i;
        int4 mm = __ldg(&g_meta[i]);         // px, lo, hi in one LDG.128
        int px = mm.x, lo = mm.y, hi = mm.z;
        const float* Drow = g_Dpz + (size_t)px * BN;   // pos-indexed

        // prefetch 6 strips: candidates (perm) and distances, both coalesced
        int   jj[6];
        float dd[6];
#pragma unroll
        for (int q = 0; q < 6; q++) {
            int idx = lo + lane + 32 * q;
            bool v = (idx < hi);
            jj[q] = v ? __ldg(g_perm + idx) : -1;
            dd[q] = v ? __ldg(Drow + idx)   : -INFINITY;
        }
        float hb = -INFINITY; int hj = 0x7fffffff;
#pragma unroll
        for (int q = 0; q < 6; q++) {
            if (jj[q] >= a) {
                float d = dd[q];
                if (d > hb || (d == hb && jj[q] < hj)) { hb = d; hj = jj[q]; }
            }
        }
        int hpos = 0;
#pragma unroll
        for (int q = 0; q < 6; q++)
            if (jj[q] == hj) hpos = lo + lane + 32 * q;
        // safety tail (class size > 192: ~never)
        for (int idx = lo + 192 + lane; idx < hi; idx += 32) {
            int j = __ldg(g_perm + idx);
            if (j >= a) {
                float d = __ldg(Drow + idx);
                if (d > hb || (d == hb && j < hj)) { hb = d; hj = j; hpos = idx; }
            }
        }
        // argmax by (value, smaller j); carry pos
        int hcode = hj;
#pragma unroll
        for (int o = 16; o; o >>= 1) {
            float v2 = __shfl_xor_sync(0xffffffffu, hb, o);
            int   c2 = __shfl_xor_sync(0xffffffffu, hcode, o);
            int   p2 = __shfl_xor_sync(0xffffffffu, hpos, o);
            if (v2 > hb || (v2 == hb && c2 < hcode)) { hb = v2; hcode = c2; hpos = p2; }
        }

        const float* dtj = g_DT + (size_t)hpos * P2;
        float nd0 = (lane      < NP) ? -__ldg(dtj + lane)      : -INFINITY;
        float nd1 = (lane + 32 < NP) ? -__ldg(dtj + lane + 32) : -INFINITY;
        float nd2 = (lane + 64 < NP) ? -__ldg(dtj + lane + 64) : -INFINITY;
        float m = fmaxf(nd0, fmaxf(nd1, nd2));
#pragma unroll
        for (int o = 16; o; o >>= 1) m = fmaxf(m, __shfl_xor_sync(0xffffffffu, m, o));
        float s = expf(nd0 - m) + expf(nd1 - m) + expf(nd2 - m);
        s = warp_sum(s);
        if (lane == 0) g_loss[i] = hb + (m + logf(s));
    }

    // ---- last block: deterministic mean ----
    __threadfence();
    __syncthreads();
    if (t == 0) s_last = (atomicAdd(&g_done, 1u) == (unsigned)(gridDim.x - 1));
    __syncthreads();
    if (s_last) {
        __threadfence();
        float s = 0.f;
        for (int k = t; k < NA; k += 256) s += g_loss[k];
        s = warp_sum(s);
        if (lane == 0) rbuf[w] = s;
        __syncthreads();
        if (t == 0) {
            float total = 0.f;
#pragma unroll
            for (int q = 0; q < 8; q++) total += rbuf[q];
            out[0] = total / (float)NA;
            g_done = 0;
        }
    }
}

// ---------------- launch ------------------------------------------------------
extern "C" void kernel_launch(void* const* d_in, const int* in_sizes, int n_in,
                              void* d_out, int out_size) {
    const float* z       = (const float*)d_in[0];
    const int*   y_idx   = (const int*)d_in[1];
    const float* proxies = (const float*)d_in[2];
    const int*   y_map   = (const int*)d_in[3];
    float*       out     = (float*)d_out;

    cudaFuncSetAttribute(k_dist, cudaFuncAttributeMaxDynamicSharedMemorySize,
                         SMEM_DYN_BYTES);
    k_pre<<<NBPRE, TPRE>>>(y_idx, y_map, proxies);
    k_dist<<<128, DTHR, SMEM_DYN_BYTES>>>(z);
    k_hard<<<HGRID, 256>>>(out);
}

// round 16
// speedup vs baseline: 1.0939x; 1.0939x over previous
#include <cuda_runtime.h>
#include <cuda_bf16.h>
#include <math.h>

#define BN     8192
#define ZD     128
#define NC     62
#define NP     93
#define P2     96        // padded proxies
#define NA     2730      // anchors 0,3,...,8187
#define EPSV   1e-6f
#define EPS2T  1.28e-10f // ZD*EPS^2
#define SZP    132       // padded smem row pitch (floats) for z AND prx
#define SDP    68        // padded dpz-transpose pitch
#define DTHR   512       // threads per block
#define NBPRE  16        // pre blocks (partial hist)
#define NBLK   (NBPRE + 128)   // 144 total, < 148 SMs -> co-resident
#define HB_W   8         // anchors (warps) per k_hard block
#define HGRID  ((NA + HB_W - 1) / HB_W)   // 342

#define SMEM_Z_FLOATS  (64 * SZP)     // 8448 (overlaid by s_dpz 96*68=6528)
#define SMEM_P_FLOATS  (P2 * SZP)     // 12672
#define SMEM_DYN_BYTES ((SMEM_Z_FLOATS + SMEM_P_FLOATS) * 4)   // 84480

// ---------------- persistent scratch (device globals, zero-init) -------------
__device__ int   g_ph[NBPRE * NC];     // partial histograms
__device__ int   g_perm[BN];           // pos -> sample index j (class-sorted)
__device__ int4  g_meta[NA];           // .x = nearest proxy, .y = lo, .z = hi
__device__ float g_Dpz[P2 * BN];       // dist(proxy p, z[perm[pos]]), [p][pos]
__device__ float g_DT [BN * P2];       // dist(z[perm[pos]], proxy p), [pos][p]
__device__ float g_loss[NA];
__device__ unsigned int g_done;
__device__ unsigned int g_preflag;     // perm-ready count; reset by k_hard
__device__ unsigned int g_barcnt;
__device__ volatile unsigned int g_bargen;   // monotonic across replays

// ---------------- helpers ---------------------------------------------------
__device__ __forceinline__ float warp_sum(float v) {
#pragma unroll
    for (int o = 16; o; o >>= 1) v += __shfl_xor_sync(0xffffffffu, v, o);
    return v;
}
__device__ __forceinline__ void warp_argmin(float& v, int& i) {
#pragma unroll
    for (int o = 16; o; o >>= 1) {
        float v2 = __shfl_xor_sync(0xffffffffu, v, o);
        int   i2 = __shfl_xor_sync(0xffffffffu, i, o);
        if (v2 < v || (v2 == v && i2 < i)) { v = v2; i = i2; }
    }
}

// ============ K1: fused perm-build + distances + nearest-proxy ===============
// grid: 144 x 512. Blocks 0..15: perm/meta. Blocks 16..143: 96x64 dist tiles.
__global__ void __launch_bounds__(DTHR) k_dist(const float* __restrict__ z,
                                               const int* __restrict__ y_idx,
                                               const int* __restrict__ y_map,
                                               const float* __restrict__ proxies) {
    extern __shared__ float smem[];
    int b = blockIdx.x, t = threadIdx.x;
    int w = t >> 5, lane = t & 31;

    if (b < NBPRE) {   // =================== PRE BLOCKS =======================
        __shared__ int s_inv[NC];
        __shared__ int s_hist[NC];
        __shared__ int s_colsum[NC], s_mine[NC], s_cur[NC];
        __shared__ int s_start[NC], s_base[NC];

        if (t < NC) { s_inv[y_map[t]] = t; s_hist[t] = 0; }
        __syncthreads();
        int myc = s_inv[y_idx[b * DTHR + t]];
        atomicAdd(&s_hist[myc], 1);
        __syncthreads();
        if (t < NC) g_ph[b * NC + t] = s_hist[t];

        // gen-barrier across the 16 pre blocks
        __syncthreads();
        if (t == 0) {
            __threadfence();
            unsigned gen = g_bargen;
            if (atomicAdd(&g_barcnt, 1u) == NBPRE - 1) {
                g_barcnt = 0;
                __threadfence();
                g_bargen = gen + 1;
            } else {
                while (g_bargen == gen) { }
            }
            __threadfence();
        }
        __syncthreads();

        if (t < NC) {
            int tot = 0, mine = 0;
#pragma unroll
            for (int bb = 0; bb < NBPRE; bb++) {
                int v = g_ph[bb * NC + t];
                if (bb < b) mine += v;
                tot += v;
            }
            s_colsum[t] = tot; s_mine[t] = mine; s_cur[t] = 0;
        }
        __syncthreads();
        if (w == 0) {   // shuffle exclusive scan of 62 totals
            int c1 = lane + 32;
            int v0 = s_colsum[lane];
            int v1 = (c1 < NC) ? s_colsum[c1] : 0;
            int x0 = v0, x1 = v1;
#pragma unroll
            for (int o = 1; o < 32; o <<= 1) {
                int y0 = __shfl_up_sync(0xffffffffu, x0, o);
                int y1 = __shfl_up_sync(0xffffffffu, x1, o);
                if (lane >= o) { x0 += y0; x1 += y1; }
            }
            int tot0 = __shfl_sync(0xffffffffu, x0, 31);
            s_start[lane] = x0 - v0;
            if (c1 < NC) s_start[c1] = tot0 + x1 - v1;
        }
        __syncthreads();
        if (t < NC) s_base[t] = s_start[t] + s_mine[t];
        __syncthreads();

        {   // scatter my slice (local rank atomics only)
            int r = atomicAdd(&s_cur[myc], 1);
            g_perm[s_base[myc] + r] = b * DTHR + t;
        }
        int gi = b * DTHR + t;
        if (gi < NA) {
            int c = s_inv[y_idx[3 * gi]];
            g_meta[gi].y = s_start[c];
            g_meta[gi].z = s_start[c] + s_colsum[c];
        }
        __syncthreads();
        if (t == 0) { __threadfence(); atomicAdd(&g_preflag, 1u); }
        return;
    }

    // =================== TILE BLOCKS =========================================
    float* s_z   = smem;                  // [64][SZP]; reused as s_dpz[96][SDP]
    float* s_prx = smem + SMEM_Z_FLOATS;  // [P2][SZP]  row-major [p][k]
    __shared__ float s_zz[64], s_zs[64];
    __shared__ float s_pss[P2], s_psum[P2];
    __shared__ int   s_perm[64];
    int B0 = (b - NBPRE) * 64;

    // ---- independent: normalize proxies into smem (overlaps pre blocks) ----
    for (int p = w; p < NP; p += 16) {
        float4 v = ((const float4*)(proxies + p * ZD))[lane];
        float ss = warp_sum(v.x * v.x + v.y * v.y + v.z * v.z + v.w * v.w);
        float inv = 1.f / fmaxf(sqrtf(ss), 1e-12f);
        float4 o = make_float4(v.x * inv, v.y * inv, v.z * inv, v.w * inv);
        *(float4*)&s_prx[p * SZP + 4 * lane] = o;
        float so  = warp_sum(o.x + o.y + o.z + o.w);
        float so2 = warp_sum(o.x * o.x + o.y * o.y + o.z * o.z + o.w * o.w);
        if (lane == 0) { s_psum[p] = so; s_pss[p] = so2; }
    }
    for (int idx = t; idx < 3 * 32; idx += DTHR)
        *(float4*)&s_prx[(NP + idx / 32) * SZP + 4 * (idx % 32)] =
            make_float4(0.f, 0.f, 0.f, 0.f);
    if (t >= NP && t < P2) { s_pss[t] = 0.f; s_psum[t] = 0.f; }

    // ---- wait for perm (usually already done) ----
    __syncthreads();
    if (t == 0) {
        while (*(volatile unsigned int*)&g_preflag < (unsigned)NBPRE) { }
    }
    __syncthreads();
    // first-ever g_perm loads this launch -> L1 miss -> L2 (fenced) : visible
    if (t < 64) s_perm[t] = g_perm[B0 + t];
    __syncthreads();

    // ---- stage 64 permuted z rows (row-coalesced; free per-row stats) ----
    const float4* z4 = (const float4*)z;
    for (int idx = t; idx < 64 * 32; idx += DTHR) {
        int r = idx >> 5, q = idx & 31;          // r warp-uniform
        float4 v = z4[(size_t)s_perm[r] * 32 + q];
        *(float4*)&s_z[r * SZP + 4 * q] = v;
        float s  = (v.x + v.y) + (v.z + v.w);
        float ss = (v.x * v.x + v.y * v.y) + (v.z * v.z + v.w * v.w);
#pragma unroll
        for (int o = 16; o; o >>= 1) {
            s  += __shfl_xor_sync(0xffffffffu, s, o);
            ss += __shfl_xor_sync(0xffffffffu, ss, o);
        }
        if (lane == 0) { s_zs[r] = s; s_zz[r] = ss; }
    }
    __syncthreads();

    // ---- mainloop: warp = samples [4w,4w+4) x 96 proxies, float4 over k ----
    int sl = 4 * w;
    const float* pr0 = &s_prx[(lane)      * SZP];
    const float* pr1 = &s_prx[(lane + 32) * SZP];
    const float* pr2 = &s_prx[(lane + 64) * SZP];
    const float* zr0 = &s_z[(sl + 0) * SZP];
    const float* zr1 = &s_z[(sl + 1) * SZP];
    const float* zr2 = &s_z[(sl + 2) * SZP];
    const float* zr3 = &s_z[(sl + 3) * SZP];

    float acc[3][4];
#pragma unroll
    for (int q = 0; q < 3; q++)
#pragma unroll
        for (int i = 0; i < 4; i++) acc[q][i] = 0.f;

#pragma unroll 4
    for (int k4 = 0; k4 < 32; k4++) {
        int ko = 4 * k4;
        float4 p0 = *(const float4*)&pr0[ko];   // conflict-free (132-pitch)
        float4 p1 = *(const float4*)&pr1[ko];
        float4 p2 = *(const float4*)&pr2[ko];
        float4 zv0 = *(const float4*)&zr0[ko];  // broadcasts
        float4 zv1 = *(const float4*)&zr1[ko];
        float4 zv2 = *(const float4*)&zr2[ko];
        float4 zv3 = *(const float4*)&zr3[ko];
#define DOT4(q, pv, i, zv) \
        acc[q][i] = fmaf(pv.x, zv.x, acc[q][i]); \
        acc[q][i] = fmaf(pv.y, zv.y, acc[q][i]); \
        acc[q][i] = fmaf(pv.z, zv.z, acc[q][i]); \
        acc[q][i] = fmaf(pv.w, zv.w, acc[q][i]);
        DOT4(0, p0, 0, zv0) DOT4(0, p0, 1, zv1) DOT4(0, p0, 2, zv2) DOT4(0, p0, 3, zv3)
        DOT4(1, p1, 0, zv0) DOT4(1, p1, 1, zv1) DOT4(1, p1, 2, zv2) DOT4(1, p1, 3, zv3)
        DOT4(2, p2, 0, zv0) DOT4(2, p2, 1, zv1) DOT4(2, p2, 2, zv2) DOT4(2, p2, 3, zv3)
#undef DOT4
    }

    // ---- epilogue: distances; DT rows direct; Dpz via smem transpose ----
    float pss0 = s_pss[lane],      psm0 = s_psum[lane];
    float pss1 = s_pss[lane + 32], psm1 = s_psum[lane + 32];
    float pss2 = s_pss[lane + 64], psm2 = s_psum[lane + 64];
    float zzv[4], zsv[4];
    int   jglob[4];
#pragma unroll
    for (int i = 0; i < 4; i++) {
        zzv[i] = s_zz[sl + i]; zsv[i] = s_zs[sl + i];
        jglob[i] = s_perm[sl + i];
    }

    __syncthreads();                       // all mainloop smem reads done
    float* s_dpz = s_z;                    // overlay: [96][SDP]

#pragma unroll
    for (int i = 0; i < 4; i++) {
        int pos = B0 + sl + i;
        float base0 = zzv[i] + pss0 - 2.f * acc[0][i];
        float base1 = zzv[i] + pss1 - 2.f * acc[1][i];
        float base2 = zzv[i] + pss2 - 2.f * acc[2][i];
        float e0 = 2.f * EPSV * (psm0 - zsv[i]);
        float e1 = 2.f * EPSV * (psm1 - zsv[i]);
        float e2 = 2.f * EPSV * (psm2 - zsv[i]);
        float dpz0 = sqrtf(fmaxf(base0 + e0 + EPS2T, 0.f));
        float dpz1 = sqrtf(fmaxf(base1 + e1 + EPS2T, 0.f));
        float dpz2 = sqrtf(fmaxf(base2 + e2 + EPS2T, 0.f));
        float dzp0 = sqrtf(fmaxf(base0 - e0 + EPS2T, 0.f));
        float dzp1 = sqrtf(fmaxf(base1 - e1 + EPS2T, 0.f));
        float dzp2 = sqrtf(fmaxf(base2 - e2 + EPS2T, 0.f));

        // DT: coalesced row writes (pos-major)
        float* dt = g_DT + (size_t)pos * P2;
        dt[lane] = dzp0; dt[lane + 32] = dzp1; dt[lane + 64] = dzp2;

        // dpz into transpose buffer
        int sc = sl + i;
        s_dpz[(lane)      * SDP + sc] = dpz0;
        s_dpz[(lane + 32) * SDP + sc] = dpz1;
        s_dpz[(lane + 64) * SDP + sc] = dpz2;

        // nearest-proxy argmin for anchor rows (dzp in registers)
        int j = jglob[i];                       // warp-uniform
        if (j % 3 == 0 && j / 3 < NA) {
            float bv = dzp0; int bp = lane;
            if (lane + 32 < NP && dzp1 < bv) { bv = dzp1; bp = lane + 32; }
            if (lane + 64 < NP && dzp2 < bv) { bv = dzp2; bp = lane + 64; }
            warp_argmin(bv, bp);
            if (lane == 0) g_meta[j / 3].x = bp;
        }
    }
    __syncthreads();

    // coalesced Dpz row writes: 96 rows x 64 floats (pos-major columns)
    for (int idx = t; idx < 96 * 16; idx += DTHR) {
        int p = idx >> 4, q = idx & 15;
        float4 v = make_float4(s_dpz[p * SDP + 4 * q],     s_dpz[p * SDP + 4 * q + 1],
                               s_dpz[p * SDP + 4 * q + 2], s_dpz[p * SDP + 4 * q + 3]);
        *(float4*)(g_Dpz + (size_t)p * BN + B0 + 4 * q) = v;
    }
}

// ============ K2: warp-per-anchor, fully coalesced candidate reads ===========
// grid: HGRID x 256
__global__ void __launch_bounds__(256) k_hard(float* __restrict__ out) {
    __shared__ float rbuf[8];
    __shared__ int s_last;
    int t = threadIdx.x, w = t >> 5, lane = t & 31;
    int i = blockIdx.x * HB_W + w;

    if (i < NA) {
        int a = 3 * i;
        int4 mm = __ldg(&g_meta[i]);         // px, lo, hi in one LDG.128
        int px = mm.x, lo = mm.y, hi = mm.z;
        const float* Drow = g_Dpz + (size_t)px * BN;   // pos-indexed

        // prefetch 6 strips: candidates (perm) and distances, both coalesced
        int   jj[6];
        float dd[6];
#pragma unroll
        for (int q = 0; q < 6; q++) {
            int idx = lo + lane + 32 * q;
            bool v = (idx < hi);
            jj[q] = v ? __ldg(g_perm + idx) : -1;
            dd[q] = v ? __ldg(Drow + idx)   : -INFINITY;
        }
        float hb = -INFINITY; int hj = 0x7fffffff;
#pragma unroll
        for (int q = 0; q < 6; q++) {
            if (jj[q] >= a) {
                float d = dd[q];
                if (d > hb || (d == hb && jj[q] < hj)) { hb = d; hj = jj[q]; }
            }
        }
        int hpos = 0;
#pragma unroll
        for (int q = 0; q < 6; q++)
            if (jj[q] == hj) hpos = lo + lane + 32 * q;
        // safety tail (class size > 192: ~never)
        for (int idx = lo + 192 + lane; idx < hi; idx += 32) {
            int j = __ldg(g_perm + idx);
            if (j >= a) {
                float d = __ldg(Drow + idx);
                if (d > hb || (d == hb && j < hj)) { hb = d; hj = j; hpos = idx; }
            }
        }
        // argmax by (value, smaller j); carry pos
        int hcode = hj;
#pragma unroll
        for (int o = 16; o; o >>= 1) {
            float v2 = __shfl_xor_sync(0xffffffffu, hb, o);
            int   c2 = __shfl_xor_sync(0xffffffffu, hcode, o);
            int   p2 = __shfl_xor_sync(0xffffffffu, hpos, o);
            if (v2 > hb || (v2 == hb && c2 < hcode)) { hb = v2; hcode = c2; hpos = p2; }
        }

        const float* dtj = g_DT + (size_t)hpos * P2;
        float nd0 = (lane      < NP) ? -__ldg(dtj + lane)      : -INFINITY;
        float nd1 = (lane + 32 < NP) ? -__ldg(dtj + lane + 32) : -INFINITY;
        float nd2 = (lane + 64 < NP) ? -__ldg(dtj + lane + 64) : -INFINITY;
        float m = fmaxf(nd0, fmaxf(nd1, nd2));
#pragma unroll
        for (int o = 16; o; o >>= 1) m = fmaxf(m, __shfl_xor_sync(0xffffffffu, m, o));
        float s = expf(nd0 - m) + expf(nd1 - m) + expf(nd2 - m);
        s = warp_sum(s);
        if (lane == 0) g_loss[i] = hb + (m + logf(s));
    }

    // ---- last block: deterministic mean + state reset ----
    __threadfence();
    __syncthreads();
    if (t == 0) s_last = (atomicAdd(&g_done, 1u) == (unsigned)(gridDim.x - 1));
    __syncthreads();
    if (s_last) {
        __threadfence();
        float s = 0.f;
        for (int k = t; k < NA; k += 256) s += g_loss[k];
        s = warp_sum(s);
        if (lane == 0) rbuf[w] = s;
        __syncthreads();
        if (t == 0) {
            float total = 0.f;
#pragma unroll
            for (int q = 0; q < 8; q++) total += rbuf[q];
            out[0] = total / (float)NA;
            g_done = 0;
            g_preflag = 0;    // re-arm perm-ready flag for next replay
        }
    }
}

// ---------------- launch ------------------------------------------------------
extern "C" void kernel_launch(void* const* d_in, const int* in_sizes, int n_in,
                              void* d_out, int out_size) {
    const float* z       = (const float*)d_in[0];
    const int*   y_idx   = (const int*)d_in[1];
    const float* proxies = (const float*)d_in[2];
    const int*   y_map   = (const int*)d_in[3];
    float*       out     = (float*)d_out;

    cudaFuncSetAttribute(k_dist, cudaFuncAttributeMaxDynamicSharedMemorySize,
                         SMEM_DYN_BYTES);
    k_dist<<<NBLK, DTHR, SMEM_DYN_BYTES>>>(z, y_idx, y_map, proxies);
    k_hard<<<HGRID, 256>>>(out);
}